// round 12
// baseline (speedup 1.0000x reference)
#include <cuda_runtime.h>
#include <cuda_fp16.h>
#include <cstdint>

// Problem constants
#define NB    32
#define NAC   5
#define NC    20
#define NH    76
#define NW    76
#define MAXT  50
#define PLANE (NH * NW)                 // 5776
#define QPP   (PLANE / 4)               // 1444 quads per plane
#define BLK   128
#define GXB   12                        // 12*128=1536 >= 1444
#define NBLOCKS (GXB * NB * NAC)        // 1920

// -------- device scratch (no allocations allowed) --------
__device__ float g_partial[NBLOCKS];
__device__ unsigned int g_counter = 0;

// sigmoid via tanh.approx: sigmoid(v) = 0.5*tanh(v/2) + 0.5  (1 MUFU op)
__device__ __forceinline__ float sigf(float v) {
    float h = 0.5f * v;
    float t;
    asm("tanh.approx.f32 %0, %1;" : "=f"(t) : "f"(h));
    return fmaf(t, 0.5f, 0.5f);
}

struct __align__(16) GT2 {
    __half2 hx;    // ( X2,  X2)
    __half2 nlx;   // (-X1, -X1)
    __half2 hy;    // ( Y2,  Y2)
    __half2 nly;   // (-Y1, -Y1)
};

__global__ __launch_bounds__(BLK, 12) void k_fused(const float* __restrict__ out,
                                                   const float* __restrict__ tgt,
                                                   const float* __restrict__ anch,
                                                   float* __restrict__ outv) {
    const int b   = blockIdx.y;
    const int a   = blockIdx.z;
    const int tid = threadIdx.x;
    const int q   = blockIdx.x * BLK + tid;
    const bool live = (q < QPP);

    __shared__ GT2     s_gt[MAXT];
    __shared__ __half2 s_nt3[MAXT];   // (-0.375*garea) duplicated
    __shared__ int     s_cnt;
    __shared__ float   red[BLK];
    __shared__ bool    isLast;

    // ---- HOISTED loads (before the barrier) ----
    const int qc  = min(q, QPP - 1);
    const int rem = qc * 4;
    const int j0  = rem / NW;
    const int i0  = rem - j0 * NW;

    const float* p = out + ((size_t)b * (NAC * 25) + a * 25) * PLANE + rem;
    float4 v0 = *(const float4*)(p);
    float4 v1 = *(const float4*)(p + PLANE);
    float4 v2 = *(const float4*)(p + 2 * PLANE);
    float4 v3 = *(const float4*)(p + 3 * PLANE);
    float4 v4 = *(const float4*)(p + 4 * PLANE);
    float aw = __ldg(&anch[2 * a]);
    float ah = __ldg(&anch[2 * a + 1]);

    if (tid == 0) s_cnt = 0;
    __syncthreads();

    // ---- per-target box prep (cheap, all blocks) ----
    float gx = 0, gy = 0, gw = 0, gh = 0;
    int   cls = 0;
    bool  valid = false;
    if (tid < MAXT) {
        const float* tp = tgt + (b * MAXT + tid) * 5;
        float f0 = tp[0], f1 = tp[1], f2 = tp[2], f3 = tp[3], f4 = tp[4];
        valid = (f1 != 0.0f);
        if (valid) {
            gx = f1 * (float)NW; gy = f2 * (float)NH;
            gw = f3 * (float)NW; gh = f4 * (float)NH;
            cls = (int)f0;
            int slot = atomicAdd(&s_cnt, 1);
            float X1 = gx - 0.5f * gw, X2 = gx + 0.5f * gw;
            float Y1 = gy - 0.5f * gh, Y2 = gy + 0.5f * gh;
            GT2 g;
            g.hx  = __float2half2_rn(X2);
            g.nlx = __float2half2_rn(-X1);
            g.hy  = __float2half2_rn(Y2);
            g.nly = __float2half2_rn(-Y1);
            s_gt[slot]  = g;
            s_nt3[slot] = __float2half2_rn(-0.375f * (gw * gh));
        }
    }
    __syncthreads();
    const int cnt = s_cnt;

    float loss = 0.0f;

    // ---- 4-cell noobj loss, packed fp16x2 (2 pairs) ----
    {
        float o0[4] = {v0.x, v0.y, v0.z, v0.w};
        float o1[4] = {v1.x, v1.y, v1.z, v1.w};
        float o2[4] = {v2.x, v2.y, v2.z, v2.w};
        float o3[4] = {v3.x, v3.y, v3.z, v3.w};
        float o4[4] = {v4.x, v4.y, v4.z, v4.w};

        float ephx[4], enplx[4], ephy[4], enply[4], thrP[4], cf[4];
        #pragma unroll
        for (int c = 0; c < 4; c++) {
            float x = sigf(o0[c]);
            float y = sigf(o1[c]);
            cf[c]   = sigf(o4[c]);
            float px = x + (float)(i0 + c);
            float py = y + (float)j0;
            float pw = __expf(o2[c]) * aw;
            float ph = __expf(o3[c]) * ah;
            ephx[c]  = px + 0.5f * pw;
            enplx[c] = 0.5f * pw - px;
            ephy[c]  = py + 0.5f * ph;
            enply[c] = 0.5f * ph - py;
            thrP[c]  = 0.375f * (pw * ph);
        }

        __half2 phx2[2], nplx2[2], phy2[2], nply2[2], m2[2];
        const __half2 z2 = __float2half2_rn(0.0f);
        const __half2 mI = __float2half2_rn(-60000.0f);
        #pragma unroll
        for (int pp = 0; pp < 2; pp++) {
            phx2[pp]  = __floats2half2_rn(ephx[2*pp],  ephx[2*pp+1]);
            nplx2[pp] = __floats2half2_rn(enplx[2*pp], enplx[2*pp+1]);
            phy2[pp]  = __floats2half2_rn(ephy[2*pp],  ephy[2*pp+1]);
            nply2[pp] = __floats2half2_rn(enply[2*pp], enply[2*pp+1]);
            m2[pp]    = mI;
        }

        #define SIL_STEP(t)                                                   \
        {                                                                     \
            GT2 g = s_gt[t];                                                  \
            __half2 nt3 = s_nt3[t];                                           \
            _Pragma("unroll")                                                 \
            for (int pp = 0; pp < 2; pp++) {                                  \
                __half2 iw  = __hadd2(__hmin2(phx2[pp], g.hx),                \
                                      __hmin2(nplx2[pp], g.nlx));             \
                __half2 ih  = __hadd2(__hmin2(phy2[pp], g.hy),                \
                                      __hmin2(nply2[pp], g.nly));             \
                __half2 iwc = __hmax2(iw, z2);                                \
                m2[pp] = __hmax2(m2[pp], __hfma2(iwc, ih, nt3));              \
            }                                                                 \
        }

        if (cnt == 12) {
            #pragma unroll
            for (int t = 0; t < 12; t++) SIL_STEP(t)
        } else {
            for (int t = 0; t < cnt; t++) SIL_STEP(t)
        }
        #undef SIL_STEP

        if (live) {
            #pragma unroll
            for (int pp = 0; pp < 2; pp++) {
                float mlo = __low2float(m2[pp]);
                float mhi = __high2float(m2[pp]);
                loss += (mlo > thrP[2*pp])   ? 0.0f : 0.5f * cf[2*pp]   * cf[2*pp];
                loss += (mhi > thrP[2*pp+1]) ? 0.0f : 0.5f * cf[2*pp+1] * cf[2*pp+1];
            }
        }
    }

    // ---- matched-cell loss: one block per image handles its 12 GTs ----
    if (blockIdx.x == 0 && blockIdx.z == 0 && valid) {
        float ga = gw * gh;
        float best = -1.0f; int bn = 0;
        #pragma unroll
        for (int an = 0; an < NAC; an++) {
            float aww = __ldg(&anch[2 * an]), ahh = __ldg(&anch[2 * an + 1]);
            float ca  = fminf(gw, aww) * fminf(gh, ahh);
            float iou = ca / (ga + aww * ahh - ca);
            if (iou > best) { best = iou; bn = an; }
        }
        float aww = __ldg(&anch[2 * bn]), ahh = __ldg(&anch[2 * bn + 1]);
        int gi = min(max((int)gx, 0), NW - 1);
        int gj = min(max((int)gy, 0), NH - 1);
        float txv = gx - (float)gi;
        float tyv = gy - (float)gj;
        float twv = __logf(gw / aww);
        float thv = __logf(gh / ahh);

        const float* pm = out + ((size_t)b * (NAC * 25) + bn * 25) * PLANE + gj * NW + gi;
        float o0 = pm[0];
        float o1 = pm[PLANE];
        float o2 = pm[2 * PLANE];
        float o3 = pm[3 * PLANE];
        float o4 = pm[4 * PLANE];
        float x = sigf(o0), y = sigf(o1), conf = sigf(o4);
        float px = x + (float)gi;
        float py = y + (float)gj;
        float pw = __expf(o2) * aww;
        float ph = __expf(o3) * ahh;

        // tconf = iou(gt, pred) — fp32
        float iw = fminf(px + 0.5f * pw, gx + 0.5f * gw) - fmaxf(px - 0.5f * pw, gx - 0.5f * gw);
        float ih = fminf(py + 0.5f * ph, gy + 0.5f * gh) - fmaxf(py - 0.5f * ph, gy - 0.5f * gh);
        float ca = (iw <= 0.0f || ih <= 0.0f) ? 0.0f : iw * ih;
        float tconf = ca / (pw * ph + ga - ca);

        // silence mirror — IDENTICAL half2 arithmetic as main loop
        float thrPm = 0.375f * (pw * ph);
        __half2 phx2m  = __floats2half2_rn(px + 0.5f * pw, px + 0.5f * pw);
        __half2 nplx2m = __floats2half2_rn(0.5f * pw - px, 0.5f * pw - px);
        __half2 phy2m  = __floats2half2_rn(py + 0.5f * ph, py + 0.5f * ph);
        __half2 nply2m = __floats2half2_rn(0.5f * ph - py, 0.5f * ph - py);
        const __half2 z2 = __float2half2_rn(0.0f);
        __half2 m2m = __float2half2_rn(-60000.0f);
        for (int t = 0; t < cnt; t++) {
            GT2 g = s_gt[t];
            __half2 nt3 = s_nt3[t];
            __half2 iw2 = __hadd2(__hmin2(phx2m, g.hx), __hmin2(nplx2m, g.nlx));
            __half2 ih2 = __hadd2(__hmin2(phy2m, g.hy), __hmin2(nply2m, g.nly));
            __half2 iwc = __hmax2(iw2, z2);
            m2m = __hmax2(m2m, __hfma2(iwc, ih2, nt3));
        }
        float mM = __low2float(m2m);
        float keepTerm = (mM > thrPm) ? 0.0f : 0.5f * conf * conf;

        // cross-entropy over 20 classes, two-pass — fp32
        float mx = -1e30f;
        #pragma unroll
        for (int c = 0; c < NC; c++) mx = fmaxf(mx, pm[(5 + c) * PLANE]);
        float se = 0.0f;
        #pragma unroll
        for (int c = 0; c < NC; c++) se += __expf(pm[(5 + c) * PLANE] - mx);
        float ce = (__logf(se) + mx) - pm[(5 + cls) * PLANE];

        float dx = x  - txv, dy = y  - tyv;
        float dw = o2 - twv, dh = o3 - thv;
        float dc = conf - tconf;
        loss += 0.5f * (dx * dx + dy * dy + dw * dw + dh * dh)
              + 2.5f * dc * dc
              + ce
              - keepTerm;   // cancel main-loop noobj term (bit-exact mirror)
    }

    // ---- block reduction ----
    red[tid] = loss;
    __syncthreads();
    #pragma unroll
    for (int s = BLK / 2; s > 32; s >>= 1) {
        if (tid < s) red[tid] += red[tid + s];
        __syncthreads();
    }
    if (tid < 32) {
        float v = red[tid] + red[tid + 32];
        #pragma unroll
        for (int off = 16; off > 0; off >>= 1)
            v += __shfl_down_sync(0xFFFFFFFFu, v, off);
        if (tid == 0) {
            int bidx = (blockIdx.z * NB + blockIdx.y) * GXB + blockIdx.x;
            g_partial[bidx] = v;
        }
    }

    // ---- last-block final reduction ----
    if (tid == 0) {
        __threadfence();
        unsigned int v = atomicAdd(&g_counter, 1u);
        isLast = (v == (unsigned int)(NBLOCKS - 1));
    }
    __syncthreads();
    if (isLast) {
        double acc = 0.0;
        for (int i2 = tid; i2 < NBLOCKS; i2 += BLK) acc += (double)g_partial[i2];
        __shared__ double dred[BLK];
        dred[tid] = acc;
        __syncthreads();
        #pragma unroll
        for (int s = BLK / 2; s > 0; s >>= 1) {
            if (tid < s) dred[tid] += dred[tid + s];
            __syncthreads();
        }
        if (tid == 0) {
            outv[0] = (float)(dred[0] / (double)NB);
            g_counter = 0;   // reset for next graph replay
        }
    }
}

extern "C" void kernel_launch(void* const* d_in, const int* in_sizes, int n_in,
                              void* d_out, int out_size) {
    const float* out  = (const float*)d_in[0];
    const float* tgt  = (const float*)d_in[1];
    const float* anch = (const float*)d_in[2];
    float* o = (float*)d_out;

    dim3 g(GXB, NB, NAC);
    k_fused<<<g, BLK>>>(out, tgt, anch, o);
}

// round 13
// speedup vs baseline: 1.1552x; 1.1552x over previous
#include <cuda_runtime.h>
#include <cuda_fp16.h>
#include <cstdint>

// Problem constants
#define NB    32
#define NAC   5
#define NC    20
#define NH    76
#define NW    76
#define MAXT  50
#define PLANE (NH * NW)                 // 5776
#define NOCT  722                       // threads per plane; each does 8 cells
#define BLK   128
#define GXB   6                         // 6*128=768 >= 722
#define NBLOCKS (GXB * NB * NAC)        // 960  (single wave)

// -------- device scratch (no allocations allowed) --------
__device__ float g_partial[NBLOCKS];
__device__ unsigned int g_counter = 0;

// fp32 sigmoid via tanh.approx (matched-cell path only)
__device__ __forceinline__ float sigf(float v) {
    float h = 0.5f * v;
    float t;
    asm("tanh.approx.f32 %0, %1;" : "=f"(t) : "f"(h));
    return fmaf(t, 0.5f, 0.5f);
}

// ---- packed fp16x2 transcendentals ----
__device__ __forceinline__ __half2 tanh2(__half2 v) {
    uint32_t ri = *reinterpret_cast<uint32_t*>(&v), ro;
    asm("tanh.approx.f16x2 %0, %1;" : "=r"(ro) : "r"(ri));
    return *reinterpret_cast<__half2*>(&ro);
}
__device__ __forceinline__ __half2 ex2h2(__half2 v) {
    uint32_t ri = *reinterpret_cast<uint32_t*>(&v), ro;
    asm("ex2.approx.f16x2 %0, %1;" : "=r"(ro) : "r"(ri));
    return *reinterpret_cast<__half2*>(&ro);
}
__device__ __forceinline__ __half2 sig2(__half2 v) {
    const __half2 h05 = __float2half2_rn(0.5f);
    return __hfma2(tanh2(__hmul2(v, h05)), h05, h05);
}

// full per-pair prep in half2 (2 cells per op)
__device__ __forceinline__ void prep_pair(
    float o0a, float o0b, float o1a, float o1b, float o2a, float o2b,
    float o3a, float o3b, float o4a, float o4b, float ia, float ib, float jj,
    __half2 aw2, __half2 ah2,
    __half2& phx, __half2& nplx, __half2& phy, __half2& nply,
    __half2& thr, __half2& cf)
{
    const __half2 h05 = __float2half2_rn(0.5f);
    const __half2 l2e = __float2half2_rn(1.44269504f);
    const __half2 c38 = __float2half2_rn(0.375f);
    __half2 O0 = __floats2half2_rn(o0a, o0b);
    __half2 O1 = __floats2half2_rn(o1a, o1b);
    __half2 O2 = __floats2half2_rn(o2a, o2b);
    __half2 O3 = __floats2half2_rn(o3a, o3b);
    __half2 O4 = __floats2half2_rn(o4a, o4b);
    __half2 x = sig2(O0);
    __half2 y = sig2(O1);
    cf = sig2(O4);
    __half2 pw = __hmul2(ex2h2(__hmul2(O2, l2e)), aw2);
    __half2 ph = __hmul2(ex2h2(__hmul2(O3, l2e)), ah2);
    __half2 px = __hadd2(x, __floats2half2_rn(ia, ib));
    __half2 py = __hadd2(y, __float2half2_rn(jj));
    phx  = __hfma2(pw, h05, px);
    nplx = __hfma2(pw, h05, __hneg2(px));
    phy  = __hfma2(ph, h05, py);
    nply = __hfma2(ph, h05, __hneg2(py));
    thr  = __hmul2(__hmul2(pw, ph), c38);
}

struct __align__(16) GT2 {
    __half2 hx;    // ( X2,  X2)
    __half2 nlx;   // (-X1, -X1)
    __half2 hy;    // ( Y2,  Y2)
    __half2 nly;   // (-Y1, -Y1)
};

__global__ __launch_bounds__(BLK, 7) void k_fused(const float* __restrict__ out,
                                                  const float* __restrict__ tgt,
                                                  const float* __restrict__ anch,
                                                  float* __restrict__ outv) {
    const int b   = blockIdx.y;
    const int a   = blockIdx.z;
    const int tid = threadIdx.x;
    const int q   = blockIdx.x * BLK + tid;
    const bool live = (q < NOCT);

    __shared__ GT2     s_gt[MAXT];
    __shared__ __half2 s_nt3[MAXT];   // (-0.375*garea) duplicated
    __shared__ int     s_cnt;
    __shared__ float   red[BLK];
    __shared__ bool    isLast;

    // ---- HOISTED loads for BOTH quads (MLP=10) ----
    const int qc   = min(q, NOCT - 1);
    const int remA = qc * 4;                 // quad A
    const int remB = remA + 4 * NOCT;        // quad B
    const int jA   = remA / NW;
    const int iA   = remA - jA * NW;
    const int jB   = remB / NW;
    const int iB   = remB - jB * NW;

    const float* base = out + ((size_t)b * (NAC * 25) + a * 25) * PLANE;
    const float* pA = base + remA;
    const float* pB = base + remB;
    float4 a0 = *(const float4*)(pA);
    float4 a1 = *(const float4*)(pA + PLANE);
    float4 a2 = *(const float4*)(pA + 2 * PLANE);
    float4 a3 = *(const float4*)(pA + 3 * PLANE);
    float4 a4 = *(const float4*)(pA + 4 * PLANE);
    float4 b0 = *(const float4*)(pB);
    float4 b1 = *(const float4*)(pB + PLANE);
    float4 b2 = *(const float4*)(pB + 2 * PLANE);
    float4 b3 = *(const float4*)(pB + 3 * PLANE);
    float4 b4 = *(const float4*)(pB + 4 * PLANE);
    float aw = __ldg(&anch[2 * a]);
    float ah = __ldg(&anch[2 * a + 1]);

    if (tid == 0) s_cnt = 0;
    __syncthreads();

    // ---- per-target box prep (cheap, all blocks) ----
    float gx = 0, gy = 0, gw = 0, gh = 0;
    int   cls = 0;
    bool  valid = false;
    if (tid < MAXT) {
        const float* tp = tgt + (b * MAXT + tid) * 5;
        float f0 = tp[0], f1 = tp[1], f2 = tp[2], f3 = tp[3], f4 = tp[4];
        valid = (f1 != 0.0f);
        if (valid) {
            gx = f1 * (float)NW; gy = f2 * (float)NH;
            gw = f3 * (float)NW; gh = f4 * (float)NH;
            cls = (int)f0;
            int slot = atomicAdd(&s_cnt, 1);
            float X1 = gx - 0.5f * gw, X2 = gx + 0.5f * gw;
            float Y1 = gy - 0.5f * gh, Y2 = gy + 0.5f * gh;
            GT2 g;
            g.hx  = __float2half2_rn(X2);
            g.nlx = __float2half2_rn(-X1);
            g.hy  = __float2half2_rn(Y2);
            g.nly = __float2half2_rn(-Y1);
            s_gt[slot]  = g;
            s_nt3[slot] = __float2half2_rn(-0.375f * (gw * gh));
        }
    }
    __syncthreads();
    const int cnt = s_cnt;

    const __half2 aw2 = __float2half2_rn(aw);
    const __half2 ah2 = __float2half2_rn(ah);

    float loss = 0.0f;

    // ---- merged 8-cell noobj loss, fully packed fp16x2 (4 pairs) ----
    {
        __half2 phx2[4], nplx2[4], phy2[4], nply2[4], thr2[4], cf2[4], m2[4];
        const __half2 z2 = __float2half2_rn(0.0f);
        const __half2 mI = __float2half2_rn(-60000.0f);

        prep_pair(a0.x, a0.y, a1.x, a1.y, a2.x, a2.y, a3.x, a3.y, a4.x, a4.y,
                  (float)(iA + 0), (float)(iA + 1), (float)jA, aw2, ah2,
                  phx2[0], nplx2[0], phy2[0], nply2[0], thr2[0], cf2[0]);
        prep_pair(a0.z, a0.w, a1.z, a1.w, a2.z, a2.w, a3.z, a3.w, a4.z, a4.w,
                  (float)(iA + 2), (float)(iA + 3), (float)jA, aw2, ah2,
                  phx2[1], nplx2[1], phy2[1], nply2[1], thr2[1], cf2[1]);
        prep_pair(b0.x, b0.y, b1.x, b1.y, b2.x, b2.y, b3.x, b3.y, b4.x, b4.y,
                  (float)(iB + 0), (float)(iB + 1), (float)jB, aw2, ah2,
                  phx2[2], nplx2[2], phy2[2], nply2[2], thr2[2], cf2[2]);
        prep_pair(b0.z, b0.w, b1.z, b1.w, b2.z, b2.w, b3.z, b3.w, b4.z, b4.w,
                  (float)(iB + 2), (float)(iB + 3), (float)jB, aw2, ah2,
                  phx2[3], nplx2[3], phy2[3], nply2[3], thr2[3], cf2[3]);

        #pragma unroll
        for (int pp = 0; pp < 4; pp++) m2[pp] = mI;

        #define SIL_STEP(t)                                                   \
        {                                                                     \
            GT2 g = s_gt[t];                                                  \
            __half2 nt3 = s_nt3[t];                                           \
            _Pragma("unroll")                                                 \
            for (int pp = 0; pp < 4; pp++) {                                  \
                __half2 iw  = __hadd2(__hmin2(phx2[pp], g.hx),                \
                                      __hmin2(nplx2[pp], g.nlx));             \
                __half2 ih  = __hadd2(__hmin2(phy2[pp], g.hy),                \
                                      __hmin2(nply2[pp], g.nly));             \
                __half2 iwc = __hmax2(iw, z2);                                \
                m2[pp] = __hmax2(m2[pp], __hfma2(iwc, ih, nt3));              \
            }                                                                 \
        }

        if (cnt == 12) {
            #pragma unroll
            for (int t = 0; t < 12; t++) SIL_STEP(t)
        } else {
            for (int t = 0; t < cnt; t++) SIL_STEP(t)
        }
        #undef SIL_STEP

        if (live) {
            #pragma unroll
            for (int pp = 0; pp < 4; pp++) {
                __half2 mask = __hle2(m2[pp], thr2[pp]);   // keep where m <= thr
                __half2 t2 = __hmul2(__hmul2(cf2[pp], cf2[pp]), mask);
                float2 tf = __half22float2(t2);
                loss += 0.5f * (tf.x + tf.y);
            }
        }
    }

    // ---- matched-cell loss: one block per image handles its 12 GTs ----
    if (blockIdx.x == 0 && blockIdx.z == 0 && valid) {
        float ga = gw * gh;
        float best = -1.0f; int bn = 0;
        #pragma unroll
        for (int an = 0; an < NAC; an++) {
            float aww = __ldg(&anch[2 * an]), ahh = __ldg(&anch[2 * an + 1]);
            float ca  = fminf(gw, aww) * fminf(gh, ahh);
            float iou = ca / (ga + aww * ahh - ca);
            if (iou > best) { best = iou; bn = an; }
        }
        float aww = __ldg(&anch[2 * bn]), ahh = __ldg(&anch[2 * bn + 1]);
        int gi = min(max((int)gx, 0), NW - 1);
        int gj = min(max((int)gy, 0), NH - 1);
        float txv = gx - (float)gi;
        float tyv = gy - (float)gj;
        float twv = __logf(gw / aww);
        float thv = __logf(gh / ahh);

        const float* pm = out + ((size_t)b * (NAC * 25) + bn * 25) * PLANE + gj * NW + gi;
        float o0 = pm[0];
        float o1 = pm[PLANE];
        float o2 = pm[2 * PLANE];
        float o3 = pm[3 * PLANE];
        float o4 = pm[4 * PLANE];
        // fp32 path for reference-accurate coord/conf losses
        float x = sigf(o0), y = sigf(o1), conf = sigf(o4);
        float px = x + (float)gi;
        float py = y + (float)gj;
        float pw = __expf(o2) * aww;
        float ph = __expf(o3) * ahh;

        // tconf = iou(gt, pred) — fp32
        float iw = fminf(px + 0.5f * pw, gx + 0.5f * gw) - fmaxf(px - 0.5f * pw, gx - 0.5f * gw);
        float ih = fminf(py + 0.5f * ph, gy + 0.5f * gh) - fmaxf(py - 0.5f * ph, gy - 0.5f * gh);
        float ca = (iw <= 0.0f || ih <= 0.0f) ? 0.0f : iw * ih;
        float tconf = ca / (pw * ph + ga - ca);

        // silence + noobj mirror — IDENTICAL half2 pipeline, value paired with itself
        __half2 aw2m = __float2half2_rn(aww);
        __half2 ah2m = __float2half2_rn(ahh);
        __half2 phx2m, nplx2m, phy2m, nply2m, thr2m, cf2m;
        prep_pair(o0, o0, o1, o1, o2, o2, o3, o3, o4, o4,
                  (float)gi, (float)gi, (float)gj, aw2m, ah2m,
                  phx2m, nplx2m, phy2m, nply2m, thr2m, cf2m);
        const __half2 z2 = __float2half2_rn(0.0f);
        __half2 m2m = __float2half2_rn(-60000.0f);
        for (int t = 0; t < cnt; t++) {
            GT2 g = s_gt[t];
            __half2 nt3 = s_nt3[t];
            __half2 iw2 = __hadd2(__hmin2(phx2m, g.hx), __hmin2(nplx2m, g.nlx));
            __half2 ih2 = __hadd2(__hmin2(phy2m, g.hy), __hmin2(nply2m, g.nly));
            __half2 iwc = __hmax2(iw2, z2);
            m2m = __hmax2(m2m, __hfma2(iwc, ih2, nt3));
        }
        __half2 maskm = __hle2(m2m, thr2m);
        __half2 t2m = __hmul2(__hmul2(cf2m, cf2m), maskm);
        float keepTerm = 0.5f * __low2float(t2m);

        // cross-entropy over 20 classes, two-pass — fp32
        float mx = -1e30f;
        #pragma unroll
        for (int c = 0; c < NC; c++) mx = fmaxf(mx, pm[(5 + c) * PLANE]);
        float se = 0.0f;
        #pragma unroll
        for (int c = 0; c < NC; c++) se += __expf(pm[(5 + c) * PLANE] - mx);
        float ce = (__logf(se) + mx) - pm[(5 + cls) * PLANE];

        float dx = x  - txv, dy = y  - tyv;
        float dw = o2 - twv, dh = o3 - thv;
        float dc = conf - tconf;
        loss += 0.5f * (dx * dx + dy * dy + dw * dw + dh * dh)
              + 2.5f * dc * dc
              + ce
              - keepTerm;   // cancel main-loop noobj term (bit-exact mirror)
    }

    // ---- block reduction ----
    red[tid] = loss;
    __syncthreads();
    #pragma unroll
    for (int s = BLK / 2; s > 32; s >>= 1) {
        if (tid < s) red[tid] += red[tid + s];
        __syncthreads();
    }
    if (tid < 32) {
        float v = red[tid] + red[tid + 32];
        #pragma unroll
        for (int off = 16; off > 0; off >>= 1)
            v += __shfl_down_sync(0xFFFFFFFFu, v, off);
        if (tid == 0) {
            int bidx = (blockIdx.z * NB + blockIdx.y) * GXB + blockIdx.x;
            g_partial[bidx] = v;
        }
    }

    // ---- last-block final reduction ----
    if (tid == 0) {
        __threadfence();
        unsigned int v = atomicAdd(&g_counter, 1u);
        isLast = (v == (unsigned int)(NBLOCKS - 1));
    }
    __syncthreads();
    if (isLast) {
        double acc = 0.0;
        for (int i2 = tid; i2 < NBLOCKS; i2 += BLK) acc += (double)g_partial[i2];
        __shared__ double dred[BLK];
        dred[tid] = acc;
        __syncthreads();
        #pragma unroll
        for (int s = BLK / 2; s > 0; s >>= 1) {
            if (tid < s) dred[tid] += dred[tid + s];
            __syncthreads();
        }
        if (tid == 0) {
            outv[0] = (float)(dred[0] / (double)NB);
            g_counter = 0;   // reset for next graph replay
        }
    }
}

extern "C" void kernel_launch(void* const* d_in, const int* in_sizes, int n_in,
                              void* d_out, int out_size) {
    const float* out  = (const float*)d_in[0];
    const float* tgt  = (const float*)d_in[1];
    const float* anch = (const float*)d_in[2];
    float* o = (float*)d_out;

    dim3 g(GXB, NB, NAC);
    k_fused<<<g, BLK>>>(out, tgt, anch, o);
}

// round 14
// speedup vs baseline: 1.1858x; 1.0265x over previous
#include <cuda_runtime.h>
#include <cuda_fp16.h>
#include <cstdint>

// Problem constants
#define NB    32
#define NAC   5
#define NC    20
#define NH    76
#define NW    76
#define MAXT  50
#define PLANE (NH * NW)                 // 5776
#define NOCT  722                       // threads per plane; each does 8 cells
#define BLK   128
#define GXB   6                         // 6*128=768 >= 722
#define NBLOCKS (GXB * NB * NAC)        // 960  (single wave)

// -------- device scratch (no allocations allowed) --------
__device__ float g_partial[NBLOCKS];
__device__ unsigned int g_counter = 0;

// fp32 sigmoid via tanh.approx (matched-cell path only)
__device__ __forceinline__ float sigf(float v) {
    float h = 0.5f * v;
    float t;
    asm("tanh.approx.f32 %0, %1;" : "=f"(t) : "f"(h));
    return fmaf(t, 0.5f, 0.5f);
}

// ---- packed fp16x2 transcendentals ----
__device__ __forceinline__ __half2 tanh2(__half2 v) {
    uint32_t ri = *reinterpret_cast<uint32_t*>(&v), ro;
    asm("tanh.approx.f16x2 %0, %1;" : "=r"(ro) : "r"(ri));
    return *reinterpret_cast<__half2*>(&ro);
}
__device__ __forceinline__ __half2 ex2h2(__half2 v) {
    uint32_t ri = *reinterpret_cast<uint32_t*>(&v), ro;
    asm("ex2.approx.f16x2 %0, %1;" : "=r"(ro) : "r"(ri));
    return *reinterpret_cast<__half2*>(&ro);
}
__device__ __forceinline__ __half2 sig2(__half2 v) {
    const __half2 h05 = __float2half2_rn(0.5f);
    return __hfma2(tanh2(__hmul2(v, h05)), h05, h05);
}

// full per-pair prep in half2 (2 cells per op)
__device__ __forceinline__ void prep_pair(
    float o0a, float o0b, float o1a, float o1b, float o2a, float o2b,
    float o3a, float o3b, float o4a, float o4b, float ia, float ib, float jj,
    __half2 aw2, __half2 ah2,
    __half2& phx, __half2& nplx, __half2& phy, __half2& nply,
    __half2& thr, __half2& cf)
{
    const __half2 h05 = __float2half2_rn(0.5f);
    const __half2 l2e = __float2half2_rn(1.44269504f);
    const __half2 c38 = __float2half2_rn(0.375f);
    __half2 O0 = __floats2half2_rn(o0a, o0b);
    __half2 O1 = __floats2half2_rn(o1a, o1b);
    __half2 O2 = __floats2half2_rn(o2a, o2b);
    __half2 O3 = __floats2half2_rn(o3a, o3b);
    __half2 O4 = __floats2half2_rn(o4a, o4b);
    __half2 x = sig2(O0);
    __half2 y = sig2(O1);
    cf = sig2(O4);
    __half2 pw = __hmul2(ex2h2(__hmul2(O2, l2e)), aw2);
    __half2 ph = __hmul2(ex2h2(__hmul2(O3, l2e)), ah2);
    __half2 px = __hadd2(x, __floats2half2_rn(ia, ib));
    __half2 py = __hadd2(y, __float2half2_rn(jj));
    phx  = __hfma2(pw, h05, px);
    nplx = __hsub2(pw, phx);      // 0.5*pw - px  (== pw - phx)
    phy  = __hfma2(ph, h05, py);
    nply = __hsub2(ph, phy);      // 0.5*ph - py
    thr  = __hmul2(__hmul2(pw, ph), c38);
}

struct __align__(16) GT2 {
    __half2 hx;    // ( X2,  X2)
    __half2 nlx;   // (-X1, -X1)
    __half2 hy;    // ( Y2,  Y2)
    __half2 nly;   // (-Y1, -Y1)
};

__global__ __launch_bounds__(BLK, 7) void k_fused(const float* __restrict__ out,
                                                  const float* __restrict__ tgt,
                                                  const float* __restrict__ anch,
                                                  float* __restrict__ outv) {
    const int b   = blockIdx.y;
    const int a   = blockIdx.z;
    const int tid = threadIdx.x;
    const int q   = blockIdx.x * BLK + tid;
    const bool live = (q < NOCT);

    __shared__ GT2     s_gt[MAXT];
    __shared__ __half2 s_nt3[MAXT];   // (-0.375*garea) duplicated
    __shared__ int     s_cnt;
    __shared__ float   s_w[BLK / 32];
    __shared__ bool    isLast;

    // ---- HOISTED loads: main data for BOTH quads (MLP=10) + target row ----
    const int qc   = min(q, NOCT - 1);
    const int remA = qc * 4;                 // quad A
    const int remB = remA + 4 * NOCT;        // quad B
    const int jA   = remA / NW;
    const int iA   = remA - jA * NW;
    const int jB   = remB / NW;
    const int iB   = remB - jB * NW;

    const float* base = out + ((size_t)b * (NAC * 25) + a * 25) * PLANE;
    const float* pA = base + remA;
    const float* pB = base + remB;
    float4 a0 = *(const float4*)(pA);
    float4 a1 = *(const float4*)(pA + PLANE);
    float4 a2 = *(const float4*)(pA + 2 * PLANE);
    float4 a3 = *(const float4*)(pA + 3 * PLANE);
    float4 a4 = *(const float4*)(pA + 4 * PLANE);
    float4 b0 = *(const float4*)(pB);
    float4 b1 = *(const float4*)(pB + PLANE);
    float4 b2 = *(const float4*)(pB + 2 * PLANE);
    float4 b3 = *(const float4*)(pB + 3 * PLANE);
    float4 b4 = *(const float4*)(pB + 4 * PLANE);
    float aw = __ldg(&anch[2 * a]);
    float ah = __ldg(&anch[2 * a + 1]);

    // target row loads hoisted (latency overlaps main-data fetch)
    float f0 = 0, f1 = 0, f2 = 0, f3 = 0, f4 = 0;
    if (tid < MAXT) {
        const float* tp = tgt + (b * MAXT + tid) * 5;
        f0 = tp[0]; f1 = tp[1]; f2 = tp[2]; f3 = tp[3]; f4 = tp[4];
    }

    if (tid == 0) s_cnt = 0;
    __syncthreads();

    // ---- per-target box prep (cheap, all blocks) ----
    float gx = 0, gy = 0, gw = 0, gh = 0;
    int   cls = 0;
    bool  valid = false;
    if (tid < MAXT) {
        valid = (f1 != 0.0f);
        if (valid) {
            gx = f1 * (float)NW; gy = f2 * (float)NH;
            gw = f3 * (float)NW; gh = f4 * (float)NH;
            cls = (int)f0;
            int slot = atomicAdd(&s_cnt, 1);
            float X1 = gx - 0.5f * gw, X2 = gx + 0.5f * gw;
            float Y1 = gy - 0.5f * gh, Y2 = gy + 0.5f * gh;
            GT2 g;
            g.hx  = __float2half2_rn(X2);
            g.nlx = __float2half2_rn(-X1);
            g.hy  = __float2half2_rn(Y2);
            g.nly = __float2half2_rn(-Y1);
            s_gt[slot]  = g;
            s_nt3[slot] = __float2half2_rn(-0.375f * (gw * gh));
        }
    }
    __syncthreads();
    const int cnt = s_cnt;

    const __half2 aw2 = __float2half2_rn(aw);
    const __half2 ah2 = __float2half2_rn(ah);

    float loss = 0.0f;

    // ---- merged 8-cell noobj loss, fully packed fp16x2 (4 pairs) ----
    {
        __half2 phx2[4], nplx2[4], phy2[4], nply2[4], thr2[4], cf2[4], m2[4];
        const __half2 z2 = __float2half2_rn(0.0f);
        const __half2 mI = __float2half2_rn(-60000.0f);

        prep_pair(a0.x, a0.y, a1.x, a1.y, a2.x, a2.y, a3.x, a3.y, a4.x, a4.y,
                  (float)(iA + 0), (float)(iA + 1), (float)jA, aw2, ah2,
                  phx2[0], nplx2[0], phy2[0], nply2[0], thr2[0], cf2[0]);
        prep_pair(a0.z, a0.w, a1.z, a1.w, a2.z, a2.w, a3.z, a3.w, a4.z, a4.w,
                  (float)(iA + 2), (float)(iA + 3), (float)jA, aw2, ah2,
                  phx2[1], nplx2[1], phy2[1], nply2[1], thr2[1], cf2[1]);
        prep_pair(b0.x, b0.y, b1.x, b1.y, b2.x, b2.y, b3.x, b3.y, b4.x, b4.y,
                  (float)(iB + 0), (float)(iB + 1), (float)jB, aw2, ah2,
                  phx2[2], nplx2[2], phy2[2], nply2[2], thr2[2], cf2[2]);
        prep_pair(b0.z, b0.w, b1.z, b1.w, b2.z, b2.w, b3.z, b3.w, b4.z, b4.w,
                  (float)(iB + 2), (float)(iB + 3), (float)jB, aw2, ah2,
                  phx2[3], nplx2[3], phy2[3], nply2[3], thr2[3], cf2[3]);

        #pragma unroll
        for (int pp = 0; pp < 4; pp++) m2[pp] = mI;

        #define SIL_STEP(t)                                                   \
        {                                                                     \
            GT2 g = s_gt[t];                                                  \
            __half2 nt3 = s_nt3[t];                                           \
            _Pragma("unroll")                                                 \
            for (int pp = 0; pp < 4; pp++) {                                  \
                __half2 iw  = __hadd2(__hmin2(phx2[pp], g.hx),                \
                                      __hmin2(nplx2[pp], g.nlx));             \
                __half2 ih  = __hadd2(__hmin2(phy2[pp], g.hy),                \
                                      __hmin2(nply2[pp], g.nly));             \
                __half2 iwc = __hmax2(iw, z2);                                \
                m2[pp] = __hmax2(m2[pp], __hfma2(iwc, ih, nt3));              \
            }                                                                 \
        }

        if (cnt == 12) {
            #pragma unroll
            for (int t = 0; t < 12; t++) SIL_STEP(t)
        } else {
            for (int t = 0; t < cnt; t++) SIL_STEP(t)
        }
        #undef SIL_STEP

        if (live) {
            __half2 acc2 = z2;
            #pragma unroll
            for (int pp = 0; pp < 4; pp++) {
                __half2 mask = __hle2(m2[pp], thr2[pp]);   // keep where m <= thr
                acc2 = __hfma2(__hmul2(cf2[pp], cf2[pp]), mask, acc2);
            }
            float2 af = __half22float2(acc2);
            loss += 0.5f * (af.x + af.y);
        }
    }

    // ---- matched-cell loss: one block per image handles its 12 GTs ----
    if (blockIdx.x == 0 && blockIdx.z == 0 && valid) {
        float ga = gw * gh;
        float best = -1.0f; int bn = 0;
        #pragma unroll
        for (int an = 0; an < NAC; an++) {
            float aww = __ldg(&anch[2 * an]), ahh = __ldg(&anch[2 * an + 1]);
            float ca  = fminf(gw, aww) * fminf(gh, ahh);
            float iou = ca / (ga + aww * ahh - ca);
            if (iou > best) { best = iou; bn = an; }
        }
        float aww = __ldg(&anch[2 * bn]), ahh = __ldg(&anch[2 * bn + 1]);
        int gi = min(max((int)gx, 0), NW - 1);
        int gj = min(max((int)gy, 0), NH - 1);
        float txv = gx - (float)gi;
        float tyv = gy - (float)gj;
        float twv = __logf(gw / aww);
        float thv = __logf(gh / ahh);

        const float* pm = out + ((size_t)b * (NAC * 25) + bn * 25) * PLANE + gj * NW + gi;
        float o0 = pm[0];
        float o1 = pm[PLANE];
        float o2 = pm[2 * PLANE];
        float o3 = pm[3 * PLANE];
        float o4 = pm[4 * PLANE];
        // fp32 path for reference-accurate coord/conf losses
        float x = sigf(o0), y = sigf(o1), conf = sigf(o4);
        float px = x + (float)gi;
        float py = y + (float)gj;
        float pw = __expf(o2) * aww;
        float ph = __expf(o3) * ahh;

        // tconf = iou(gt, pred) — fp32
        float iw = fminf(px + 0.5f * pw, gx + 0.5f * gw) - fmaxf(px - 0.5f * pw, gx - 0.5f * gw);
        float ih = fminf(py + 0.5f * ph, gy + 0.5f * gh) - fmaxf(py - 0.5f * ph, gy - 0.5f * gh);
        float ca = (iw <= 0.0f || ih <= 0.0f) ? 0.0f : iw * ih;
        float tconf = ca / (pw * ph + ga - ca);

        // silence + noobj mirror — IDENTICAL half2 pipeline, value paired with itself
        __half2 aw2m = __float2half2_rn(aww);
        __half2 ah2m = __float2half2_rn(ahh);
        __half2 phx2m, nplx2m, phy2m, nply2m, thr2m, cf2m;
        prep_pair(o0, o0, o1, o1, o2, o2, o3, o3, o4, o4,
                  (float)gi, (float)gi, (float)gj, aw2m, ah2m,
                  phx2m, nplx2m, phy2m, nply2m, thr2m, cf2m);
        const __half2 z2 = __float2half2_rn(0.0f);
        __half2 m2m = __float2half2_rn(-60000.0f);
        for (int t = 0; t < cnt; t++) {
            GT2 g = s_gt[t];
            __half2 nt3 = s_nt3[t];
            __half2 iw2 = __hadd2(__hmin2(phx2m, g.hx), __hmin2(nplx2m, g.nlx));
            __half2 ih2 = __hadd2(__hmin2(phy2m, g.hy), __hmin2(nply2m, g.nly));
            __half2 iwc = __hmax2(iw2, z2);
            m2m = __hmax2(m2m, __hfma2(iwc, ih2, nt3));
        }
        __half2 maskm = __hle2(m2m, thr2m);
        __half2 t2m = __hmul2(__hmul2(cf2m, cf2m), maskm);
        float keepTerm = 0.5f * __low2float(t2m);

        // cross-entropy over 20 classes, two-pass — fp32
        float mx = -1e30f;
        #pragma unroll
        for (int c = 0; c < NC; c++) mx = fmaxf(mx, pm[(5 + c) * PLANE]);
        float se = 0.0f;
        #pragma unroll
        for (int c = 0; c < NC; c++) se += __expf(pm[(5 + c) * PLANE] - mx);
        float ce = (__logf(se) + mx) - pm[(5 + cls) * PLANE];

        float dx = x  - txv, dy = y  - tyv;
        float dw = o2 - twv, dh = o3 - thv;
        float dc = conf - tconf;
        loss += 0.5f * (dx * dx + dy * dy + dw * dw + dh * dh)
              + 2.5f * dc * dc
              + ce
              - keepTerm;   // cancel main-loop noobj term (bit-exact mirror)
    }

    // ---- block reduction: warp shuffle first, one barrier ----
    {
        float v = loss;
        #pragma unroll
        for (int off = 16; off > 0; off >>= 1)
            v += __shfl_down_sync(0xFFFFFFFFu, v, off);
        if ((tid & 31) == 0) s_w[tid >> 5] = v;
    }
    __syncthreads();
    if (tid == 0) {
        float r = (s_w[0] + s_w[1]) + (s_w[2] + s_w[3]);
        int bidx = (blockIdx.z * NB + blockIdx.y) * GXB + blockIdx.x;
        g_partial[bidx] = r;
        __threadfence();
        unsigned int v = atomicAdd(&g_counter, 1u);
        isLast = (v == (unsigned int)(NBLOCKS - 1));
    }
    __syncthreads();

    // ---- last-block final reduction ----
    if (isLast) {
        double acc = 0.0;
        for (int i2 = tid; i2 < NBLOCKS; i2 += BLK) acc += (double)g_partial[i2];
        __shared__ double dred[BLK];
        dred[tid] = acc;
        __syncthreads();
        #pragma unroll
        for (int s = BLK / 2; s > 0; s >>= 1) {
            if (tid < s) dred[tid] += dred[tid + s];
            __syncthreads();
        }
        if (tid == 0) {
            outv[0] = (float)(dred[0] / (double)NB);
            g_counter = 0;   // reset for next graph replay
        }
    }
}

extern "C" void kernel_launch(void* const* d_in, const int* in_sizes, int n_in,
                              void* d_out, int out_size) {
    const float* out  = (const float*)d_in[0];
    const float* tgt  = (const float*)d_in[1];
    const float* anch = (const float*)d_in[2];
    float* o = (float*)d_out;

    dim3 g(GXB, NB, NAC);
    k_fused<<<g, BLK>>>(out, tgt, anch, o);
}